// round 4
// baseline (speedup 1.0000x reference)
#include <cuda_runtime.h>

// ---------------------------------------------------------------------------
// GraphProbeFeatures: fused per-batch SIREN + probe projections + LayerNorm.
// R4: 1024 threads/CTA (8 warps/SMSP, was 4) with per-thread tiles halved so
// regs fit 64/thread; accurate sinf -> __sinf (MUFU) to kill serial poly chains.
// One CTA per batch b (grid=128, ~204KB dynamic smem). Streams N=4096 points
// in tiles of 64; z1/z2 [128x128] accumulators in packed f32x2 register pairs.
// ---------------------------------------------------------------------------

namespace gpf {
constexpr int Bn   = 128;
constexpr int Nn   = 4096;
constexpr int Hh   = 128;
constexpr int Pp   = 128;
constexpr int DOUT = 3;
constexpr int ROWS = 2 + Hh + Hh + DOUT;   // 261 output rows per batch
constexpr int TILE = 64;
constexpr int NTILES = Nn / TILE;          // 64
constexpr int NTHREADS = 1024;
constexpr int HS   = 136;                  // padded row stride for h tiles
constexpr float W0F = 30.0f;
constexpr float EPS = 1e-5f;

// shared-memory layout (float offsets)
constexpr int OFF_W1  = 0;                       // 128x128 w1 (stride 128)
constexpr int OFF_H1  = OFF_W1  + Hh * Hh;       // 64x136
constexpr int OFF_H2  = OFF_H1  + TILE * HS;     // 64x136
constexpr int OFF_PW1 = OFF_H2  + TILE * HS;     // 64x128  (also zs epilogue, with OFF_PW2)
constexpr int OFF_PW2 = OFF_PW1 + TILE * Pp;     // 64x128
constexpr int OFF_W0  = OFF_PW2 + TILE * Pp;     // 2x128
constexpr int OFF_B0  = OFF_W0  + 2 * Hh;        // 128
constexpr int OFF_B1  = OFF_B0  + Hh;            // 128
constexpr int OFF_W2  = OFF_B1  + Hh;            // 128x4 (stride 4, col 3 unused)
constexpr int OFF_B2  = OFF_W2  + Hh * 4;        // 4
constexpr int OFF_H3  = OFF_B2  + 4;             // 64x4
constexpr int OFF_Z5  = OFF_H3  + TILE * 4;      // 5x128 (z0 rows + z3 rows)
constexpr int SMEM_FLOATS = OFF_Z5 + 5 * Pp;     // 52100 floats
constexpr int SMEM_BYTES  = SMEM_FLOATS * 4;     // 208400 B
}  // namespace gpf

// ---- packed f32x2 helpers --------------------------------------------------
__device__ __forceinline__ unsigned long long pk2(float x, float y) {
    unsigned long long r;
    asm("mov.b64 %0, {%1, %2};" : "=l"(r) : "f"(x), "f"(y));
    return r;
}
__device__ __forceinline__ float2 upk2(unsigned long long v) {
    float2 f;
    asm("mov.b64 {%0, %1}, %2;" : "=f"(f.x), "=f"(f.y) : "l"(v));
    return f;
}
__device__ __forceinline__ void fma2(unsigned long long& acc,
                                     unsigned long long a, unsigned long long b) {
    asm("fma.rn.f32x2 %0, %1, %2, %0;" : "+l"(acc) : "l"(a), "l"(b));
}

// ---- warp LayerNorm over one row of 128 (lane holds 4 contiguous values) ---
__device__ __forceinline__ void ln_row_write(float4 v, const float* __restrict__ g,
                                             const float* __restrict__ bb,
                                             float* __restrict__ orow, int lane) {
    float s = (v.x + v.y) + (v.z + v.w);
    #pragma unroll
    for (int o = 16; o > 0; o >>= 1) s += __shfl_xor_sync(0xffffffffu, s, o);
    float m = s * (1.0f / 128.0f);
    float cx = v.x - m, cy = v.y - m, cz = v.z - m, cw = v.w - m;
    float q = (cx * cx + cy * cy) + (cz * cz + cw * cw);
    #pragma unroll
    for (int o = 16; o > 0; o >>= 1) q += __shfl_xor_sync(0xffffffffu, q, o);
    float inv = rsqrtf(q * (1.0f / 128.0f) + gpf::EPS);
    float4 gv = *(const float4*)(g + lane * 4);
    float4 bv = *(const float4*)(bb + lane * 4);
    float4 ov;
    ov.x = cx * inv * gv.x + bv.x;
    ov.y = cy * inv * gv.y + bv.y;
    ov.z = cz * inv * gv.z + bv.z;
    ov.w = cw * inv * gv.w + bv.w;
    *(float4*)(orow + lane * 4) = ov;
}

__global__ __launch_bounds__(gpf::NTHREADS, 1)
void gpf_kernel(const float* __restrict__ w0g, const float* __restrict__ w1g,
                const float* __restrict__ w2g, const float* __restrict__ b0g,
                const float* __restrict__ b1g, const float* __restrict__ b2g,
                const float* __restrict__ xg,  const float* __restrict__ pwg,
                const float* __restrict__ pbg, const float* __restrict__ lngg,
                const float* __restrict__ lnbg, float* __restrict__ outg) {
    using namespace gpf;
    extern __shared__ float sm[];
    const int b    = blockIdx.x;
    const int t    = threadIdx.x;
    const int lane = t & 31;
    const int wid  = t >> 5;   // 0..31

    float* w1s  = sm + OFF_W1;
    float* h1s  = sm + OFF_H1;
    float* h2s  = sm + OFF_H2;
    float* pw1s = sm + OFF_PW1;
    float* pw2s = sm + OFF_PW2;
    float* zs   = sm + OFF_PW1;  // epilogue reuse: 128x128
    float* w0s  = sm + OFF_W0;
    float* b0s  = sm + OFF_B0;
    float* b1s  = sm + OFF_B1;
    float* w2s  = sm + OFF_W2;
    float* b2s  = sm + OFF_B2;
    float* h3s  = sm + OFF_H3;
    float* z5s  = sm + OFF_Z5;

    // ---- one-time loads: w1 (64KB), w0/b0/b1/w2/b2 ----
    {
        const float4* src = (const float4*)(w1g + (size_t)b * Hh * Hh);
        float4* dst = (float4*)w1s;
        #pragma unroll
        for (int i = 0; i < 4; ++i) dst[t + i * NTHREADS] = src[t + i * NTHREADS];
        if (t < 256)      w0s[t]       = w0g[b * 256 + t];
        else if (t < 384) b0s[t - 256] = b0g[b * 128 + (t - 256)];
        else if (t < 512) b1s[t - 384] = b1g[b * 128 + (t - 384)];
        if (t < 128) {
            w2s[t * 4 + 0] = w2g[b * 384 + t * 3 + 0];
            w2s[t * 4 + 1] = w2g[b * 384 + t * 3 + 1];
            w2s[t * 4 + 2] = w2g[b * 384 + t * 3 + 2];
        }
        if (t >= 512 && t < 515) b2s[t - 512] = b2g[b * 3 + (t - 512)];
    }

    // ---- persistent accumulators ----
    // az*[pair][j] = packed ( z[d0+2*pair][p0+j], z[d0+2*pair+1][p0+j] )
    unsigned long long az1[2][4], az2[2][4];
    #pragma unroll
    for (int i = 0; i < 2; ++i)
        #pragma unroll
        for (int j = 0; j < 4; ++j) { az1[i][j] = 0ull; az2[i][j] = 0ull; }
    float z3acc = 0.0f;  // valid for t < 384:  z3[j][p], j=t>>7, p=t&127
    float z0acc = 0.0f;  // valid for t < 256:  z0[d][p], d=t>>7, p=t&127

    const int d0 = wid * 4;    // z-GEMM: 4 d-rows per thread
    const int p0 = lane * 4;   //         4 p-cols per thread

    for (int tile = 0; tile < NTILES; ++tile) {
        const int n0 = tile * TILE;
        __syncthreads();  // previous tile's consumers done before overwriting tiles

        // ---- Phase A: h1 tile (layer 1 + sin) and pw1/pw2 tiles ----
        #pragma unroll
        for (int it = 0; it < 8; ++it) {
            int idx = t + it * NTHREADS;          // 0..8191
            int n = idx >> 7, h = idx & 127;
            float x0 = xg[(n0 + n) * 2 + 0];
            float x1 = xg[(n0 + n) * 2 + 1];
            float a = fmaf(x0, w0s[h], fmaf(x1, w0s[128 + h], b0s[h]));
            h1s[n * HS + h] = __sinf(W0F * a);
        }
        {
            const float4* s1 = (const float4*)(pwg + (size_t)1 * Nn * Pp + (size_t)n0 * Pp);
            const float4* s2 = (const float4*)(pwg + (size_t)2 * Nn * Pp + (size_t)n0 * Pp);
            float4* dt1 = (float4*)pw1s;
            float4* dt2 = (float4*)pw2s;
            #pragma unroll
            for (int it = 0; it < 2; ++it) {
                dt1[t + it * NTHREADS] = s1[t + it * NTHREADS];
                dt2[t + it * NTHREADS] = s2[t + it * NTHREADS];
            }
        }
        __syncthreads();

        // ---- Phase B: h2 = sin(30*(h1 @ w1 + b1)), 2n x 4o per thread ----
        {
            const int nb = wid * 2;
            const int ob = lane * 4;
            unsigned long long acc[2][2];
            acc[0][0] = acc[0][1] = acc[1][0] = acc[1][1] = 0ull;
            #pragma unroll 4
            for (int k = 0; k < Hh; ++k) {
                ulonglong2 bp = *(const ulonglong2*)(w1s + k * Hh + ob);
                float a0 = h1s[nb * HS + k];
                float a1 = h1s[(nb + 1) * HS + k];
                unsigned long long ad0 = pk2(a0, a0);
                unsigned long long ad1 = pk2(a1, a1);
                fma2(acc[0][0], ad0, bp.x);
                fma2(acc[0][1], ad0, bp.y);
                fma2(acc[1][0], ad1, bp.x);
                fma2(acc[1][1], ad1, bp.y);
            }
            float bb0 = b1s[ob], bb1 = b1s[ob + 1], bb2 = b1s[ob + 2], bb3 = b1s[ob + 3];
            #pragma unroll
            for (int i = 0; i < 2; ++i) {
                float2 u = upk2(acc[i][0]);
                float2 v = upk2(acc[i][1]);
                float4 o;
                o.x = __sinf(W0F * (u.x + bb0));
                o.y = __sinf(W0F * (u.y + bb1));
                o.z = __sinf(W0F * (v.x + bb2));
                o.w = __sinf(W0F * (v.y + bb3));
                *(float4*)(h2s + (nb + i) * HS + ob) = o;
            }
        }

        // ---- Phase C: z1 += h1^T @ pw1 (reads only h1s; hoisted above the
        //      h2-consumer barrier so the barrier hides behind this FMA stream) ----
        #pragma unroll 4
        for (int n = 0; n < TILE; ++n) {
            ulonglong2 A = *(const ulonglong2*)(h1s + n * HS + d0);
            float4 bv = *(const float4*)(pw1s + n * Pp + p0);
            unsigned long long bd0 = pk2(bv.x, bv.x), bd1 = pk2(bv.y, bv.y);
            unsigned long long bd2 = pk2(bv.z, bv.z), bd3 = pk2(bv.w, bv.w);
            fma2(az1[0][0], A.x, bd0); fma2(az1[0][1], A.x, bd1);
            fma2(az1[0][2], A.x, bd2); fma2(az1[0][3], A.x, bd3);
            fma2(az1[1][0], A.y, bd0); fma2(az1[1][1], A.y, bd1);
            fma2(az1[1][2], A.y, bd2); fma2(az1[1][3], A.y, bd3);
        }

        // h2s fully written (Phase B) before ANY thread reads other warps' rows
        __syncthreads();

        // ---- Phase E (t<192): h3[n][j] = h2[n,:] . w2[:,j] + b2[j] ----
        if (t < 192) {
            int n = t / 3;
            int j = t - n * 3;
            float acc = b2s[j];
            #pragma unroll 8
            for (int k = 0; k < Hh; ++k)
                acc = fmaf(h2s[n * HS + k], w2s[k * 4 + j], acc);
            h3s[n * 4 + j] = acc;
        }

        // ---- Phase D: z2 += h2^T @ pw2 ----
        #pragma unroll 4
        for (int n = 0; n < TILE; ++n) {
            ulonglong2 A = *(const ulonglong2*)(h2s + n * HS + d0);
            float4 bv = *(const float4*)(pw2s + n * Pp + p0);
            unsigned long long bd0 = pk2(bv.x, bv.x), bd1 = pk2(bv.y, bv.y);
            unsigned long long bd2 = pk2(bv.z, bv.z), bd3 = pk2(bv.w, bv.w);
            fma2(az2[0][0], A.x, bd0); fma2(az2[0][1], A.x, bd1);
            fma2(az2[0][2], A.x, bd2); fma2(az2[0][3], A.x, bd3);
            fma2(az2[1][0], A.y, bd0); fma2(az2[1][1], A.y, bd1);
            fma2(az2[1][2], A.y, bd2); fma2(az2[1][3], A.y, bd3);
        }
        __syncthreads();

        // ---- Phase F: z3 += h3^T @ pw3 (pw3 streamed from L2) ----
        if (t < 384) {
            int j = t >> 7, p = t & 127;
            const float* pw3 = pwg + (size_t)3 * Nn * Pp + (size_t)n0 * Pp + p;
            float ta = 0.0f, tb = 0.0f;
            #pragma unroll 8
            for (int n = 0; n < TILE; n += 2) {
                ta = fmaf(h3s[n * 4 + j],       pw3[n * Pp],       ta);
                tb = fmaf(h3s[(n + 1) * 4 + j], pw3[(n + 1) * Pp], tb);
            }
            z3acc += ta + tb;
        }
        // ---- z0 partial: z0 += x_tile^T @ pw0 (x, pw0 streamed from L2) ----
        if (t < 256) {
            int dd = t >> 7, p = t & 127;
            const float* pw0 = pwg + (size_t)n0 * Pp + p;
            const float* xp  = xg + n0 * 2 + dd;
            float ta = 0.0f, tb = 0.0f;
            #pragma unroll 8
            for (int n = 0; n < TILE; n += 2) {
                ta = fmaf(xp[n * 2],       pw0[n * Pp],       ta);
                tb = fmaf(xp[(n + 1) * 2], pw0[(n + 1) * Pp], tb);
            }
            z0acc += ta + tb;
        }
    }

    // =========================== epilogue ===========================
    __syncthreads();

    // ---- feat1 (h1 projection): rows 2..129 ----
    {
        const float* pb1 = pbg + 128;
        float q0 = pb1[p0], q1 = pb1[p0 + 1], q2 = pb1[p0 + 2], q3 = pb1[p0 + 3];
        #pragma unroll
        for (int di = 0; di < 2; ++di) {
            float2 a0 = upk2(az1[di][0]);
            float2 a1 = upk2(az1[di][1]);
            float2 a2 = upk2(az1[di][2]);
            float2 a3 = upk2(az1[di][3]);
            float4 r0 = {a0.x + q0, a1.x + q1, a2.x + q2, a3.x + q3};
            float4 r1 = {a0.y + q0, a1.y + q1, a2.y + q2, a3.y + q3};
            *(float4*)(zs + (d0 + 2 * di) * Pp + p0)     = r0;
            *(float4*)(zs + (d0 + 2 * di + 1) * Pp + p0) = r1;
        }
    }
    __syncthreads();
    {
        const float* g  = lngg + 128;
        const float* bb = lnbg + 128;
        #pragma unroll
        for (int r = 0; r < 4; ++r) {
            int row = wid * 4 + r;
            float4 v = *(const float4*)(zs + row * Pp + lane * 4);
            ln_row_write(v, g, bb, outg + ((size_t)b * ROWS + 2 + row) * Pp, lane);
        }
    }
    __syncthreads();

    // ---- feat2 (h2 projection): rows 130..257 ----
    {
        const float* pb2 = pbg + 256;
        float q0 = pb2[p0], q1 = pb2[p0 + 1], q2 = pb2[p0 + 2], q3 = pb2[p0 + 3];
        #pragma unroll
        for (int di = 0; di < 2; ++di) {
            float2 a0 = upk2(az2[di][0]);
            float2 a1 = upk2(az2[di][1]);
            float2 a2 = upk2(az2[di][2]);
            float2 a3 = upk2(az2[di][3]);
            float4 r0 = {a0.x + q0, a1.x + q1, a2.x + q2, a3.x + q3};
            float4 r1 = {a0.y + q0, a1.y + q1, a2.y + q2, a3.y + q3};
            *(float4*)(zs + (d0 + 2 * di) * Pp + p0)     = r0;
            *(float4*)(zs + (d0 + 2 * di + 1) * Pp + p0) = r1;
        }
    }
    __syncthreads();
    {
        const float* g  = lngg + 256;
        const float* bb = lnbg + 256;
        #pragma unroll
        for (int r = 0; r < 4; ++r) {
            int row = wid * 4 + r;
            float4 v = *(const float4*)(zs + row * Pp + lane * 4);
            ln_row_write(v, g, bb, outg + ((size_t)b * ROWS + 130 + row) * Pp, lane);
        }
    }

    // ---- feat0 (x projection, rows 0..1) and feat3 (h3 projection, rows 258..260) ----
    if (t < 256) {
        int dd = t >> 7, p = t & 127;
        z5s[dd * Pp + p] = z0acc + pbg[p];
    }
    if (t < 384) {
        int j = t >> 7, p = t & 127;
        z5s[(2 + j) * Pp + p] = z3acc + pbg[3 * 128 + p];
    }
    __syncthreads();
    if (wid < 5) {
        int row    = wid;                       // 0,1 -> z0 ; 2,3,4 -> z3
        int feat   = (row < 2) ? 0 : 3;
        int outrow = (row < 2) ? row : (256 + row);  // 258,259,260
        float4 v = *(const float4*)(z5s + row * Pp + lane * 4);
        ln_row_write(v, lngg + feat * 128, lnbg + feat * 128,
                     outg + ((size_t)b * ROWS + outrow) * Pp, lane);
    }
}

extern "C" void kernel_launch(void* const* d_in, const int* in_sizes, int n_in,
                              void* d_out, int out_size) {
    (void)in_sizes; (void)n_in; (void)out_size;
    const float* w0g  = (const float*)d_in[0];
    const float* w1g  = (const float*)d_in[1];
    const float* w2g  = (const float*)d_in[2];
    const float* b0g  = (const float*)d_in[3];
    const float* b1g  = (const float*)d_in[4];
    const float* b2g  = (const float*)d_in[5];
    const float* xg   = (const float*)d_in[6];
    const float* pwg  = (const float*)d_in[7];
    const float* pbg  = (const float*)d_in[8];
    const float* lngg = (const float*)d_in[9];
    const float* lnbg = (const float*)d_in[10];
    float* outg = (float*)d_out;

    cudaFuncSetAttribute(gpf_kernel, cudaFuncAttributeMaxDynamicSharedMemorySize,
                         gpf::SMEM_BYTES);
    gpf_kernel<<<gpf::Bn, gpf::NTHREADS, gpf::SMEM_BYTES>>>(
        w0g, w1g, w2g, b0g, b1g, b2g, xg, pwg, pbg, lngg, lnbg, outg);
}

// round 5
// speedup vs baseline: 1.3028x; 1.3028x over previous
#include <cuda_runtime.h>

// ---------------------------------------------------------------------------
// GraphProbeFeatures: fused per-batch SIREN + probe projections + LayerNorm.
// R5: revert to 512-thread / 8x4-tile structure (R3) which balances smem
// crossbar vs fma issue; keep __sinf; Phase B loads h1 as float4 broadcasts
// (crossbar 8->5 cyc/k/warp); tail phases (E / z3 / z0) spread across
// disjoint warp groups to cut barrier imbalance.
// ---------------------------------------------------------------------------

namespace gpf {
constexpr int Bn   = 128;
constexpr int Nn   = 4096;
constexpr int Hh   = 128;
constexpr int Pp   = 128;
constexpr int DOUT = 3;
constexpr int ROWS = 2 + Hh + Hh + DOUT;   // 261 output rows per batch
constexpr int TILE = 64;
constexpr int NTILES = Nn / TILE;          // 64
constexpr int NTHREADS = 512;
constexpr int HS   = 136;                  // padded row stride for h tiles
constexpr float W0F = 30.0f;
constexpr float EPS = 1e-5f;

// shared-memory layout (float offsets)
constexpr int OFF_W1  = 0;                       // 128x128 w1 (stride 128)
constexpr int OFF_H1  = OFF_W1  + Hh * Hh;       // 64x136
constexpr int OFF_H2  = OFF_H1  + TILE * HS;     // 64x136
constexpr int OFF_PW1 = OFF_H2  + TILE * HS;     // 64x128  (also zs epilogue, with OFF_PW2)
constexpr int OFF_PW2 = OFF_PW1 + TILE * Pp;     // 64x128
constexpr int OFF_W0  = OFF_PW2 + TILE * Pp;     // 2x128
constexpr int OFF_B0  = OFF_W0  + 2 * Hh;        // 128
constexpr int OFF_B1  = OFF_B0  + Hh;            // 128
constexpr int OFF_W2  = OFF_B1  + Hh;            // 128x4 (stride 4, col 3 unused)
constexpr int OFF_B2  = OFF_W2  + Hh * 4;        // 4
constexpr int OFF_H3  = OFF_B2  + 4;             // 64x4
constexpr int OFF_Z5  = OFF_H3  + TILE * 4;      // 5x128 (z0 rows + z3 rows)
constexpr int SMEM_FLOATS = OFF_Z5 + 5 * Pp;     // 52100 floats
constexpr int SMEM_BYTES  = SMEM_FLOATS * 4;     // 208400 B
}  // namespace gpf

// ---- packed f32x2 helpers --------------------------------------------------
__device__ __forceinline__ unsigned long long pk2(float x, float y) {
    unsigned long long r;
    asm("mov.b64 %0, {%1, %2};" : "=l"(r) : "f"(x), "f"(y));
    return r;
}
__device__ __forceinline__ float2 upk2(unsigned long long v) {
    float2 f;
    asm("mov.b64 {%0, %1}, %2;" : "=f"(f.x), "=f"(f.y) : "l"(v));
    return f;
}
__device__ __forceinline__ void fma2(unsigned long long& acc,
                                     unsigned long long a, unsigned long long b) {
    asm("fma.rn.f32x2 %0, %1, %2, %0;" : "+l"(acc) : "l"(a), "l"(b));
}

// ---- warp LayerNorm over one row of 128 (lane holds 4 contiguous values) ---
__device__ __forceinline__ void ln_row_write(float4 v, const float* __restrict__ g,
                                             const float* __restrict__ bb,
                                             float* __restrict__ orow, int lane) {
    float s = (v.x + v.y) + (v.z + v.w);
    #pragma unroll
    for (int o = 16; o > 0; o >>= 1) s += __shfl_xor_sync(0xffffffffu, s, o);
    float m = s * (1.0f / 128.0f);
    float cx = v.x - m, cy = v.y - m, cz = v.z - m, cw = v.w - m;
    float q = (cx * cx + cy * cy) + (cz * cz + cw * cw);
    #pragma unroll
    for (int o = 16; o > 0; o >>= 1) q += __shfl_xor_sync(0xffffffffu, q, o);
    float inv = rsqrtf(q * (1.0f / 128.0f) + gpf::EPS);
    float4 gv = *(const float4*)(g + lane * 4);
    float4 bv = *(const float4*)(bb + lane * 4);
    float4 ov;
    ov.x = cx * inv * gv.x + bv.x;
    ov.y = cy * inv * gv.y + bv.y;
    ov.z = cz * inv * gv.z + bv.z;
    ov.w = cw * inv * gv.w + bv.w;
    *(float4*)(orow + lane * 4) = ov;
}

__global__ __launch_bounds__(gpf::NTHREADS, 1)
void gpf_kernel(const float* __restrict__ w0g, const float* __restrict__ w1g,
                const float* __restrict__ w2g, const float* __restrict__ b0g,
                const float* __restrict__ b1g, const float* __restrict__ b2g,
                const float* __restrict__ xg,  const float* __restrict__ pwg,
                const float* __restrict__ pbg, const float* __restrict__ lngg,
                const float* __restrict__ lnbg, float* __restrict__ outg) {
    using namespace gpf;
    extern __shared__ float sm[];
    const int b    = blockIdx.x;
    const int t    = threadIdx.x;
    const int lane = t & 31;
    const int wid  = t >> 5;   // 0..15

    float* w1s  = sm + OFF_W1;
    float* h1s  = sm + OFF_H1;
    float* h2s  = sm + OFF_H2;
    float* pw1s = sm + OFF_PW1;
    float* pw2s = sm + OFF_PW2;
    float* zs   = sm + OFF_PW1;  // epilogue reuse: 128x128
    float* w0s  = sm + OFF_W0;
    float* b0s  = sm + OFF_B0;
    float* b1s  = sm + OFF_B1;
    float* w2s  = sm + OFF_W2;
    float* b2s  = sm + OFF_B2;
    float* h3s  = sm + OFF_H3;
    float* z5s  = sm + OFF_Z5;

    // ---- one-time loads: w1 (64KB), w0/b0/b1/w2/b2 ----
    {
        const float4* src = (const float4*)(w1g + (size_t)b * Hh * Hh);
        float4* dst = (float4*)w1s;
        #pragma unroll
        for (int i = 0; i < 8; ++i) dst[t + i * NTHREADS] = src[t + i * NTHREADS];
        if (t < 256)      w0s[t]       = w0g[b * 256 + t];
        else if (t < 384) b0s[t - 256] = b0g[b * 128 + (t - 256)];
        else              b1s[t - 384] = b1g[b * 128 + (t - 384)];
        if (t < 128) {
            w2s[t * 4 + 0] = w2g[b * 384 + t * 3 + 0];
            w2s[t * 4 + 1] = w2g[b * 384 + t * 3 + 1];
            w2s[t * 4 + 2] = w2g[b * 384 + t * 3 + 2];
        }
        if (t < 3) b2s[t] = b2g[b * 3 + t];
    }

    // ---- persistent accumulators ----
    // az*[di][j] = packed pair ( z[d0+2*di][p0+j], z[d0+2*di+1][p0+j] )
    unsigned long long az1[4][4], az2[4][4];
    #pragma unroll
    for (int i = 0; i < 4; ++i)
        #pragma unroll
        for (int j = 0; j < 4; ++j) { az1[i][j] = 0ull; az2[i][j] = 0ull; }
    float z3acc  = 0.0f;  // valid for t < 384:   z3[j][p], j=t>>7, p=t&127
    float z0acc0 = 0.0f;  // valid for t >= 384:  z0[0][p], p=t-384
    float z0acc1 = 0.0f;  // valid for t >= 384:  z0[1][p], p=t-384

    const int d0 = wid * 8;    // z-GEMM: 8 d-rows per thread
    const int p0 = lane * 4;   //         4 p-cols per thread

    for (int tile = 0; tile < NTILES; ++tile) {
        const int n0 = tile * TILE;
        __syncthreads();  // previous tile's consumers done before overwriting tiles

        // ---- Phase A: h1 tile (layer 1 + sin) and pw1/pw2 tiles ----
        #pragma unroll
        for (int it = 0; it < 16; ++it) {
            int idx = t + it * NTHREADS;          // 0..8191
            int n = idx >> 7, h = idx & 127;
            float x0 = xg[(n0 + n) * 2 + 0];
            float x1 = xg[(n0 + n) * 2 + 1];
            float a = fmaf(x0, w0s[h], fmaf(x1, w0s[128 + h], b0s[h]));
            h1s[n * HS + h] = __sinf(W0F * a);
        }
        {
            const float4* s1 = (const float4*)(pwg + (size_t)1 * Nn * Pp + (size_t)n0 * Pp);
            const float4* s2 = (const float4*)(pwg + (size_t)2 * Nn * Pp + (size_t)n0 * Pp);
            float4* dt1 = (float4*)pw1s;
            float4* dt2 = (float4*)pw2s;
            #pragma unroll
            for (int it = 0; it < 4; ++it) {
                dt1[t + it * NTHREADS] = s1[t + it * NTHREADS];
                dt2[t + it * NTHREADS] = s2[t + it * NTHREADS];
            }
        }
        __syncthreads();

        // ---- Phase B: h2 = sin(30*(h1 @ w1 + b1)), 4n x 4o per thread.
        //      k in blocks of 4: h1 rows fetched as float4 broadcasts (1 LDS
        //      instead of 4 scalars) -> Phase B crossbar 8->5 cyc/k/warp. ----
        {
            const int nb = wid * 4;
            const int ob = lane * 4;
            unsigned long long acc[4][2];
            #pragma unroll
            for (int i = 0; i < 4; ++i) { acc[i][0] = 0ull; acc[i][1] = 0ull; }
            #pragma unroll 2
            for (int k4 = 0; k4 < Hh; k4 += 4) {
                float a0[4], a1[4], a2[4], a3[4];
                *(float4*)a0 = *(const float4*)(h1s + (nb + 0) * HS + k4);
                *(float4*)a1 = *(const float4*)(h1s + (nb + 1) * HS + k4);
                *(float4*)a2 = *(const float4*)(h1s + (nb + 2) * HS + k4);
                *(float4*)a3 = *(const float4*)(h1s + (nb + 3) * HS + k4);
                #pragma unroll
                for (int kk = 0; kk < 4; ++kk) {
                    ulonglong2 bp = *(const ulonglong2*)(w1s + (k4 + kk) * Hh + ob);
                    unsigned long long ad;
                    ad = pk2(a0[kk], a0[kk]); fma2(acc[0][0], ad, bp.x); fma2(acc[0][1], ad, bp.y);
                    ad = pk2(a1[kk], a1[kk]); fma2(acc[1][0], ad, bp.x); fma2(acc[1][1], ad, bp.y);
                    ad = pk2(a2[kk], a2[kk]); fma2(acc[2][0], ad, bp.x); fma2(acc[2][1], ad, bp.y);
                    ad = pk2(a3[kk], a3[kk]); fma2(acc[3][0], ad, bp.x); fma2(acc[3][1], ad, bp.y);
                }
            }
            float bb0 = b1s[ob], bb1 = b1s[ob + 1], bb2 = b1s[ob + 2], bb3 = b1s[ob + 3];
            #pragma unroll
            for (int i = 0; i < 4; ++i) {
                float2 u = upk2(acc[i][0]);
                float2 v = upk2(acc[i][1]);
                float4 o;
                o.x = __sinf(W0F * (u.x + bb0));
                o.y = __sinf(W0F * (u.y + bb1));
                o.z = __sinf(W0F * (v.x + bb2));
                o.w = __sinf(W0F * (v.y + bb3));
                *(float4*)(h2s + (nb + i) * HS + ob) = o;
            }
        }

        // ---- Phase C: z1 += h1^T @ pw1 (reads only h1s; hoisted above the
        //      h2-consumer barrier so the barrier hides behind this FMA stream) ----
        #pragma unroll 2
        for (int n = 0; n < TILE; ++n) {
            ulonglong2 A0 = *(const ulonglong2*)(h1s + n * HS + d0);
            ulonglong2 A1 = *(const ulonglong2*)(h1s + n * HS + d0 + 4);
            float4 bv = *(const float4*)(pw1s + n * Pp + p0);
            unsigned long long bd0 = pk2(bv.x, bv.x), bd1 = pk2(bv.y, bv.y);
            unsigned long long bd2 = pk2(bv.z, bv.z), bd3 = pk2(bv.w, bv.w);
            fma2(az1[0][0], A0.x, bd0); fma2(az1[0][1], A0.x, bd1);
            fma2(az1[0][2], A0.x, bd2); fma2(az1[0][3], A0.x, bd3);
            fma2(az1[1][0], A0.y, bd0); fma2(az1[1][1], A0.y, bd1);
            fma2(az1[1][2], A0.y, bd2); fma2(az1[1][3], A0.y, bd3);
            fma2(az1[2][0], A1.x, bd0); fma2(az1[2][1], A1.x, bd1);
            fma2(az1[2][2], A1.x, bd2); fma2(az1[2][3], A1.x, bd3);
            fma2(az1[3][0], A1.y, bd0); fma2(az1[3][1], A1.y, bd1);
            fma2(az1[3][2], A1.y, bd2); fma2(az1[3][3], A1.y, bd3);
        }

        // h2s fully written (Phase B) before ANY thread reads other warps' rows
        __syncthreads();

        // ---- Phase E (warps 10-15): h3[n][j] = h2[n,:] . w2[:,j] + b2[j] ----
        if (t >= 320) {
            int u = t - 320;               // 0..191
            int n = u / 3;
            int j = u - n * 3;
            float acc = b2s[j];
            #pragma unroll 8
            for (int k = 0; k < Hh; ++k)
                acc = fmaf(h2s[n * HS + k], w2s[k * 4 + j], acc);
            h3s[n * 4 + j] = acc;
        }

        // ---- Phase D: z2 += h2^T @ pw2 ----
        #pragma unroll 2
        for (int n = 0; n < TILE; ++n) {
            ulonglong2 A0 = *(const ulonglong2*)(h2s + n * HS + d0);
            ulonglong2 A1 = *(const ulonglong2*)(h2s + n * HS + d0 + 4);
            float4 bv = *(const float4*)(pw2s + n * Pp + p0);
            unsigned long long bd0 = pk2(bv.x, bv.x), bd1 = pk2(bv.y, bv.y);
            unsigned long long bd2 = pk2(bv.z, bv.z), bd3 = pk2(bv.w, bv.w);
            fma2(az2[0][0], A0.x, bd0); fma2(az2[0][1], A0.x, bd1);
            fma2(az2[0][2], A0.x, bd2); fma2(az2[0][3], A0.x, bd3);
            fma2(az2[1][0], A0.y, bd0); fma2(az2[1][1], A0.y, bd1);
            fma2(az2[1][2], A0.y, bd2); fma2(az2[1][3], A0.y, bd3);
            fma2(az2[2][0], A1.x, bd0); fma2(az2[2][1], A1.x, bd1);
            fma2(az2[2][2], A1.x, bd2); fma2(az2[2][3], A1.x, bd3);
            fma2(az2[3][0], A1.y, bd0); fma2(az2[3][1], A1.y, bd1);
            fma2(az2[3][2], A1.y, bd2); fma2(az2[3][3], A1.y, bd3);
        }
        __syncthreads();

        // ---- Phase F: z3 += h3^T @ pw3 on warps 0-11 (pw3 streamed from L2) ----
        if (t < 384) {
            int j = t >> 7, p = t & 127;
            const float* pw3 = pwg + (size_t)3 * Nn * Pp + (size_t)n0 * Pp + p;
            float ta = 0.0f, tb = 0.0f;
            #pragma unroll 8
            for (int n = 0; n < TILE; n += 2) {
                ta = fmaf(h3s[n * 4 + j],       pw3[n * Pp],       ta);
                tb = fmaf(h3s[(n + 1) * 4 + j], pw3[(n + 1) * Pp], tb);
            }
            z3acc += ta + tb;
        } else {
            // ---- z0 partial on warps 12-15: z0[0..1][p] += x^T @ pw0 ----
            int p = t - 384;
            const float* pw0 = pwg + (size_t)n0 * Pp + p;
            const float* xp  = xg + n0 * 2;
            float a0 = 0.0f, a1 = 0.0f;
            #pragma unroll 8
            for (int n = 0; n < TILE; ++n) {
                float w = pw0[n * Pp];
                a0 = fmaf(xp[n * 2],     w, a0);
                a1 = fmaf(xp[n * 2 + 1], w, a1);
            }
            z0acc0 += a0;
            z0acc1 += a1;
        }
    }

    // =========================== epilogue ===========================
    __syncthreads();

    // ---- feat1 (h1 projection): rows 2..129 ----
    {
        const float* pb1 = pbg + 128;
        float q0 = pb1[p0], q1 = pb1[p0 + 1], q2 = pb1[p0 + 2], q3 = pb1[p0 + 3];
        #pragma unroll
        for (int di = 0; di < 4; ++di) {
            float2 a0 = upk2(az1[di][0]);
            float2 a1 = upk2(az1[di][1]);
            float2 a2 = upk2(az1[di][2]);
            float2 a3 = upk2(az1[di][3]);
            float4 r0 = {a0.x + q0, a1.x + q1, a2.x + q2, a3.x + q3};
            float4 r1 = {a0.y + q0, a1.y + q1, a2.y + q2, a3.y + q3};
            *(float4*)(zs + (d0 + 2 * di) * Pp + p0)     = r0;
            *(float4*)(zs + (d0 + 2 * di + 1) * Pp + p0) = r1;
        }
    }
    __syncthreads();
    {
        const float* g  = lngg + 128;
        const float* bb = lnbg + 128;
        #pragma unroll
        for (int r = 0; r < 8; ++r) {
            int row = wid * 8 + r;
            float4 v = *(const float4*)(zs + row * Pp + lane * 4);
            ln_row_write(v, g, bb, outg + ((size_t)b * ROWS + 2 + row) * Pp, lane);
        }
    }
    __syncthreads();

    // ---- feat2 (h2 projection): rows 130..257 ----
    {
        const float* pb2 = pbg + 256;
        float q0 = pb2[p0], q1 = pb2[p0 + 1], q2 = pb2[p0 + 2], q3 = pb2[p0 + 3];
        #pragma unroll
        for (int di = 0; di < 4; ++di) {
            float2 a0 = upk2(az2[di][0]);
            float2 a1 = upk2(az2[di][1]);
            float2 a2 = upk2(az2[di][2]);
            float2 a3 = upk2(az2[di][3]);
            float4 r0 = {a0.x + q0, a1.x + q1, a2.x + q2, a3.x + q3};
            float4 r1 = {a0.y + q0, a1.y + q1, a2.y + q2, a3.y + q3};
            *(float4*)(zs + (d0 + 2 * di) * Pp + p0)     = r0;
            *(float4*)(zs + (d0 + 2 * di + 1) * Pp + p0) = r1;
        }
    }
    __syncthreads();
    {
        const float* g  = lngg + 256;
        const float* bb = lnbg + 256;
        #pragma unroll
        for (int r = 0; r < 8; ++r) {
            int row = wid * 8 + r;
            float4 v = *(const float4*)(zs + row * Pp + lane * 4);
            ln_row_write(v, g, bb, outg + ((size_t)b * ROWS + 130 + row) * Pp, lane);
        }
    }

    // ---- feat0 (x projection, rows 0..1) and feat3 (h3 projection, rows 258..260) ----
    if (t >= 384) {
        int p = t - 384;
        z5s[p]      = z0acc0 + pbg[p];
        z5s[Pp + p] = z0acc1 + pbg[p];
    }
    if (t < 384) {
        int j = t >> 7, p = t & 127;
        z5s[(2 + j) * Pp + p] = z3acc + pbg[3 * 128 + p];
    }
    __syncthreads();
    if (wid < 5) {
        int row    = wid;                       // 0,1 -> z0 ; 2,3,4 -> z3
        int feat   = (row < 2) ? 0 : 3;
        int outrow = (row < 2) ? row : (256 + row);  // 258,259,260
        float4 v = *(const float4*)(z5s + row * Pp + lane * 4);
        ln_row_write(v, lngg + feat * 128, lnbg + feat * 128,
                     outg + ((size_t)b * ROWS + outrow) * Pp, lane);
    }
}

extern "C" void kernel_launch(void* const* d_in, const int* in_sizes, int n_in,
                              void* d_out, int out_size) {
    (void)in_sizes; (void)n_in; (void)out_size;
    const float* w0g  = (const float*)d_in[0];
    const float* w1g  = (const float*)d_in[1];
    const float* w2g  = (const float*)d_in[2];
    const float* b0g  = (const float*)d_in[3];
    const float* b1g  = (const float*)d_in[4];
    const float* b2g  = (const float*)d_in[5];
    const float* xg   = (const float*)d_in[6];
    const float* pwg  = (const float*)d_in[7];
    const float* pbg  = (const float*)d_in[8];
    const float* lngg = (const float*)d_in[9];
    const float* lnbg = (const float*)d_in[10];
    float* outg = (float*)d_out;

    cudaFuncSetAttribute(gpf_kernel, cudaFuncAttributeMaxDynamicSharedMemorySize,
                         gpf::SMEM_BYTES);
    gpf_kernel<<<gpf::Bn, gpf::NTHREADS, gpf::SMEM_BYTES>>>(
        w0g, w1g, w2g, b0g, b1g, b2g, xg, pwg, pbg, lngg, lnbg, outg);
}

// round 6
// speedup vs baseline: 1.4110x; 1.0830x over previous
#include <cuda_runtime.h>

// ---------------------------------------------------------------------------
// GraphProbeFeatures: fused per-batch SIREN + probe projections + LayerNorm.
// R5: revert to 512-thread / 8x4-tile structure (R3) which balances smem
// crossbar vs fma issue; keep __sinf; Phase B loads h1 as float4 broadcasts
// (crossbar 8->5 cyc/k/warp); tail phases (E / z3 / z0) spread across
// disjoint warp groups to cut barrier imbalance.
// ---------------------------------------------------------------------------

namespace gpf {
constexpr int Bn   = 128;
constexpr int Nn   = 4096;
constexpr int Hh   = 128;
constexpr int Pp   = 128;
constexpr int DOUT = 3;
constexpr int ROWS = 2 + Hh + Hh + DOUT;   // 261 output rows per batch
constexpr int TILE = 64;
constexpr int NTILES = Nn / TILE;          // 64
constexpr int NTHREADS = 512;
constexpr int HS   = 136;                  // padded row stride for h tiles
constexpr float W0F = 30.0f;
constexpr float EPS = 1e-5f;

// shared-memory layout (float offsets)
constexpr int OFF_W1  = 0;                       // 128x128 w1 (stride 128)
constexpr int OFF_H1  = OFF_W1  + Hh * Hh;       // 64x136
constexpr int OFF_H2  = OFF_H1  + TILE * HS;     // 64x136
constexpr int OFF_PW1 = OFF_H2  + TILE * HS;     // 64x128  (also zs epilogue, with OFF_PW2)
constexpr int OFF_PW2 = OFF_PW1 + TILE * Pp;     // 64x128
constexpr int OFF_W0  = OFF_PW2 + TILE * Pp;     // 2x128
constexpr int OFF_B0  = OFF_W0  + 2 * Hh;        // 128
constexpr int OFF_B1  = OFF_B0  + Hh;            // 128
constexpr int OFF_W2  = OFF_B1  + Hh;            // 128x4 (stride 4, col 3 unused)
constexpr int OFF_B2  = OFF_W2  + Hh * 4;        // 4
constexpr int OFF_H3  = OFF_B2  + 4;             // 64x4
constexpr int OFF_Z5  = OFF_H3  + TILE * 4;      // 5x128 (z0 rows + z3 rows)
constexpr int SMEM_FLOATS = OFF_Z5 + 5 * Pp;     // 52100 floats
constexpr int SMEM_BYTES  = SMEM_FLOATS * 4;     // 208400 B
}  // namespace gpf

// ---- packed f32x2 helpers --------------------------------------------------
__device__ __forceinline__ unsigned long long pk2(float x, float y) {
    unsigned long long r;
    asm("mov.b64 %0, {%1, %2};" : "=l"(r) : "f"(x), "f"(y));
    return r;
}
__device__ __forceinline__ float2 upk2(unsigned long long v) {
    float2 f;
    asm("mov.b64 {%0, %1}, %2;" : "=f"(f.x), "=f"(f.y) : "l"(v));
    return f;
}
__device__ __forceinline__ void fma2(unsigned long long& acc,
                                     unsigned long long a, unsigned long long b) {
    asm("fma.rn.f32x2 %0, %1, %2, %0;" : "+l"(acc) : "l"(a), "l"(b));
}

// ---- warp LayerNorm over one row of 128 (lane holds 4 contiguous values) ---
__device__ __forceinline__ void ln_row_write(float4 v, const float* __restrict__ g,
                                             const float* __restrict__ bb,
                                             float* __restrict__ orow, int lane) {
    float s = (v.x + v.y) + (v.z + v.w);
    #pragma unroll
    for (int o = 16; o > 0; o >>= 1) s += __shfl_xor_sync(0xffffffffu, s, o);
    float m = s * (1.0f / 128.0f);
    float cx = v.x - m, cy = v.y - m, cz = v.z - m, cw = v.w - m;
    float q = (cx * cx + cy * cy) + (cz * cz + cw * cw);
    #pragma unroll
    for (int o = 16; o > 0; o >>= 1) q += __shfl_xor_sync(0xffffffffu, q, o);
    float inv = rsqrtf(q * (1.0f / 128.0f) + gpf::EPS);
    float4 gv = *(const float4*)(g + lane * 4);
    float4 bv = *(const float4*)(bb + lane * 4);
    float4 ov;
    ov.x = cx * inv * gv.x + bv.x;
    ov.y = cy * inv * gv.y + bv.y;
    ov.z = cz * inv * gv.z + bv.z;
    ov.w = cw * inv * gv.w + bv.w;
    *(float4*)(orow + lane * 4) = ov;
}

__global__ __launch_bounds__(gpf::NTHREADS, 1)
void gpf_kernel(const float* __restrict__ w0g, const float* __restrict__ w1g,
                const float* __restrict__ w2g, const float* __restrict__ b0g,
                const float* __restrict__ b1g, const float* __restrict__ b2g,
                const float* __restrict__ xg,  const float* __restrict__ pwg,
                const float* __restrict__ pbg, const float* __restrict__ lngg,
                const float* __restrict__ lnbg, float* __restrict__ outg) {
    using namespace gpf;
    extern __shared__ float sm[];
    const int b    = blockIdx.x;
    const int t    = threadIdx.x;
    const int lane = t & 31;
    const int wid  = t >> 5;   // 0..15

    float* w1s  = sm + OFF_W1;
    float* h1s  = sm + OFF_H1;
    float* h2s  = sm + OFF_H2;
    float* pw1s = sm + OFF_PW1;
    float* pw2s = sm + OFF_PW2;
    float* zs   = sm + OFF_PW1;  // epilogue reuse: 128x128
    float* w0s  = sm + OFF_W0;
    float* b0s  = sm + OFF_B0;
    float* b1s  = sm + OFF_B1;
    float* w2s  = sm + OFF_W2;
    float* b2s  = sm + OFF_B2;
    float* h3s  = sm + OFF_H3;
    float* z5s  = sm + OFF_Z5;

    // ---- one-time loads: w1 (64KB), w0/b0/b1/w2/b2 ----
    {
        const float4* src = (const float4*)(w1g + (size_t)b * Hh * Hh);
        float4* dst = (float4*)w1s;
        #pragma unroll
        for (int i = 0; i < 8; ++i) dst[t + i * NTHREADS] = src[t + i * NTHREADS];
        if (t < 256)      w0s[t]       = w0g[b * 256 + t];
        else if (t < 384) b0s[t - 256] = b0g[b * 128 + (t - 256)];
        else              b1s[t - 384] = b1g[b * 128 + (t - 384)];
        if (t < 128) {
            w2s[t * 4 + 0] = w2g[b * 384 + t * 3 + 0];
            w2s[t * 4 + 1] = w2g[b * 384 + t * 3 + 1];
            w2s[t * 4 + 2] = w2g[b * 384 + t * 3 + 2];
        }
        if (t < 3) b2s[t] = b2g[b * 3 + t];
    }

    // ---- persistent accumulators ----
    // az*[di][j] = packed pair ( z[d0+2*di][p0+j], z[d0+2*di+1][p0+j] )
    unsigned long long az1[4][4], az2[4][4];
    #pragma unroll
    for (int i = 0; i < 4; ++i)
        #pragma unroll
        for (int j = 0; j < 4; ++j) { az1[i][j] = 0ull; az2[i][j] = 0ull; }
    float z3acc  = 0.0f;  // valid for t < 384:   z3[j][p], j=t>>7, p=t&127
    float z0acc0 = 0.0f;  // valid for t >= 384:  z0[0][p], p=t-384
    float z0acc1 = 0.0f;  // valid for t >= 384:  z0[1][p], p=t-384

    const int d0 = wid * 8;    // z-GEMM: 8 d-rows per thread
    const int p0 = lane * 4;   //         4 p-cols per thread

    for (int tile = 0; tile < NTILES; ++tile) {
        const int n0 = tile * TILE;
        __syncthreads();  // previous tile's consumers done before overwriting tiles

        // ---- Phase A: h1 tile (layer 1 + sin) and pw1/pw2 tiles ----
        #pragma unroll
        for (int it = 0; it < 16; ++it) {
            int idx = t + it * NTHREADS;          // 0..8191
            int n = idx >> 7, h = idx & 127;
            float x0 = xg[(n0 + n) * 2 + 0];
            float x1 = xg[(n0 + n) * 2 + 1];
            float a = fmaf(x0, w0s[h], fmaf(x1, w0s[128 + h], b0s[h]));
            h1s[n * HS + h] = __sinf(W0F * a);
        }
        {
            const float4* s1 = (const float4*)(pwg + (size_t)1 * Nn * Pp + (size_t)n0 * Pp);
            const float4* s2 = (const float4*)(pwg + (size_t)2 * Nn * Pp + (size_t)n0 * Pp);
            float4* dt1 = (float4*)pw1s;
            float4* dt2 = (float4*)pw2s;
            #pragma unroll
            for (int it = 0; it < 4; ++it) {
                dt1[t + it * NTHREADS] = s1[t + it * NTHREADS];
                dt2[t + it * NTHREADS] = s2[t + it * NTHREADS];
            }
        }
        __syncthreads();

        // ---- Phase B: h2 = sin(30*(h1 @ w1 + b1)), 4n x 4o per thread.
        //      k in blocks of 4: h1 rows fetched as float4 broadcasts (1 LDS
        //      instead of 4 scalars) -> Phase B crossbar 8->5 cyc/k/warp. ----
        {
            const int nb = wid * 4;
            const int ob = lane * 4;
            unsigned long long acc[4][2];
            #pragma unroll
            for (int i = 0; i < 4; ++i) { acc[i][0] = 0ull; acc[i][1] = 0ull; }
            #pragma unroll 2
            for (int k4 = 0; k4 < Hh; k4 += 4) {
                float a0[4], a1[4], a2[4], a3[4];
                *(float4*)a0 = *(const float4*)(h1s + (nb + 0) * HS + k4);
                *(float4*)a1 = *(const float4*)(h1s + (nb + 1) * HS + k4);
                *(float4*)a2 = *(const float4*)(h1s + (nb + 2) * HS + k4);
                *(float4*)a3 = *(const float4*)(h1s + (nb + 3) * HS + k4);
                #pragma unroll
                for (int kk = 0; kk < 4; ++kk) {
                    ulonglong2 bp = *(const ulonglong2*)(w1s + (k4 + kk) * Hh + ob);
                    unsigned long long ad;
                    ad = pk2(a0[kk], a0[kk]); fma2(acc[0][0], ad, bp.x); fma2(acc[0][1], ad, bp.y);
                    ad = pk2(a1[kk], a1[kk]); fma2(acc[1][0], ad, bp.x); fma2(acc[1][1], ad, bp.y);
                    ad = pk2(a2[kk], a2[kk]); fma2(acc[2][0], ad, bp.x); fma2(acc[2][1], ad, bp.y);
                    ad = pk2(a3[kk], a3[kk]); fma2(acc[3][0], ad, bp.x); fma2(acc[3][1], ad, bp.y);
                }
            }
            float bb0 = b1s[ob], bb1 = b1s[ob + 1], bb2 = b1s[ob + 2], bb3 = b1s[ob + 3];
            #pragma unroll
            for (int i = 0; i < 4; ++i) {
                float2 u = upk2(acc[i][0]);
                float2 v = upk2(acc[i][1]);
                float4 o;
                o.x = __sinf(W0F * (u.x + bb0));
                o.y = __sinf(W0F * (u.y + bb1));
                o.z = __sinf(W0F * (v.x + bb2));
                o.w = __sinf(W0F * (v.y + bb3));
                *(float4*)(h2s + (nb + i) * HS + ob) = o;
            }
        }

        // ---- Phase C: z1 += h1^T @ pw1 (reads only h1s; hoisted above the
        //      h2-consumer barrier so the barrier hides behind this FMA stream) ----
        #pragma unroll 2
        for (int n = 0; n < TILE; ++n) {
            ulonglong2 A0 = *(const ulonglong2*)(h1s + n * HS + d0);
            ulonglong2 A1 = *(const ulonglong2*)(h1s + n * HS + d0 + 4);
            float4 bv = *(const float4*)(pw1s + n * Pp + p0);
            unsigned long long bd0 = pk2(bv.x, bv.x), bd1 = pk2(bv.y, bv.y);
            unsigned long long bd2 = pk2(bv.z, bv.z), bd3 = pk2(bv.w, bv.w);
            fma2(az1[0][0], A0.x, bd0); fma2(az1[0][1], A0.x, bd1);
            fma2(az1[0][2], A0.x, bd2); fma2(az1[0][3], A0.x, bd3);
            fma2(az1[1][0], A0.y, bd0); fma2(az1[1][1], A0.y, bd1);
            fma2(az1[1][2], A0.y, bd2); fma2(az1[1][3], A0.y, bd3);
            fma2(az1[2][0], A1.x, bd0); fma2(az1[2][1], A1.x, bd1);
            fma2(az1[2][2], A1.x, bd2); fma2(az1[2][3], A1.x, bd3);
            fma2(az1[3][0], A1.y, bd0); fma2(az1[3][1], A1.y, bd1);
            fma2(az1[3][2], A1.y, bd2); fma2(az1[3][3], A1.y, bd3);
        }

        // h2s fully written (Phase B) before ANY thread reads other warps' rows
        __syncthreads();

        // ---- Phase E (warps 10-15): h3[n][j] = h2[n,:] . w2[:,j] + b2[j] ----
        if (t >= 320) {
            int u = t - 320;               // 0..191
            int n = u / 3;
            int j = u - n * 3;
            float acc = b2s[j];
            #pragma unroll 8
            for (int k = 0; k < Hh; ++k)
                acc = fmaf(h2s[n * HS + k], w2s[k * 4 + j], acc);
            h3s[n * 4 + j] = acc;
        }

        // ---- Phase D: z2 += h2^T @ pw2 ----
        #pragma unroll 2
        for (int n = 0; n < TILE; ++n) {
            ulonglong2 A0 = *(const ulonglong2*)(h2s + n * HS + d0);
            ulonglong2 A1 = *(const ulonglong2*)(h2s + n * HS + d0 + 4);
            float4 bv = *(const float4*)(pw2s + n * Pp + p0);
            unsigned long long bd0 = pk2(bv.x, bv.x), bd1 = pk2(bv.y, bv.y);
            unsigned long long bd2 = pk2(bv.z, bv.z), bd3 = pk2(bv.w, bv.w);
            fma2(az2[0][0], A0.x, bd0); fma2(az2[0][1], A0.x, bd1);
            fma2(az2[0][2], A0.x, bd2); fma2(az2[0][3], A0.x, bd3);
            fma2(az2[1][0], A0.y, bd0); fma2(az2[1][1], A0.y, bd1);
            fma2(az2[1][2], A0.y, bd2); fma2(az2[1][3], A0.y, bd3);
            fma2(az2[2][0], A1.x, bd0); fma2(az2[2][1], A1.x, bd1);
            fma2(az2[2][2], A1.x, bd2); fma2(az2[2][3], A1.x, bd3);
            fma2(az2[3][0], A1.y, bd0); fma2(az2[3][1], A1.y, bd1);
            fma2(az2[3][2], A1.y, bd2); fma2(az2[3][3], A1.y, bd3);
        }
        __syncthreads();

        // ---- Phase F: z3 += h3^T @ pw3 on warps 0-11 (pw3 streamed from L2) ----
        if (t < 384) {
            int j = t >> 7, p = t & 127;
            const float* pw3 = pwg + (size_t)3 * Nn * Pp + (size_t)n0 * Pp + p;
            float ta = 0.0f, tb = 0.0f;
            #pragma unroll 8
            for (int n = 0; n < TILE; n += 2) {
                ta = fmaf(h3s[n * 4 + j],       pw3[n * Pp],       ta);
                tb = fmaf(h3s[(n + 1) * 4 + j], pw3[(n + 1) * Pp], tb);
            }
            z3acc += ta + tb;
        } else {
            // ---- z0 partial on warps 12-15: z0[0..1][p] += x^T @ pw0 ----
            int p = t - 384;
            const float* pw0 = pwg + (size_t)n0 * Pp + p;
            const float* xp  = xg + n0 * 2;
            float a0 = 0.0f, a1 = 0.0f;
            #pragma unroll 8
            for (int n = 0; n < TILE; ++n) {
                float w = pw0[n * Pp];
                a0 = fmaf(xp[n * 2],     w, a0);
                a1 = fmaf(xp[n * 2 + 1], w, a1);
            }
            z0acc0 += a0;
            z0acc1 += a1;
        }
    }

    // =========================== epilogue ===========================
    __syncthreads();

    // ---- feat1 (h1 projection): rows 2..129 ----
    {
        const float* pb1 = pbg + 128;
        float q0 = pb1[p0], q1 = pb1[p0 + 1], q2 = pb1[p0 + 2], q3 = pb1[p0 + 3];
        #pragma unroll
        for (int di = 0; di < 4; ++di) {
            float2 a0 = upk2(az1[di][0]);
            float2 a1 = upk2(az1[di][1]);
            float2 a2 = upk2(az1[di][2]);
            float2 a3 = upk2(az1[di][3]);
            float4 r0 = {a0.x + q0, a1.x + q1, a2.x + q2, a3.x + q3};
            float4 r1 = {a0.y + q0, a1.y + q1, a2.y + q2, a3.y + q3};
            *(float4*)(zs + (d0 + 2 * di) * Pp + p0)     = r0;
            *(float4*)(zs + (d0 + 2 * di + 1) * Pp + p0) = r1;
        }
    }
    __syncthreads();
    {
        const float* g  = lngg + 128;
        const float* bb = lnbg + 128;
        #pragma unroll
        for (int r = 0; r < 8; ++r) {
            int row = wid * 8 + r;
            float4 v = *(const float4*)(zs + row * Pp + lane * 4);
            ln_row_write(v, g, bb, outg + ((size_t)b * ROWS + 2 + row) * Pp, lane);
        }
    }
    __syncthreads();

    // ---- feat2 (h2 projection): rows 130..257 ----
    {
        const float* pb2 = pbg + 256;
        float q0 = pb2[p0], q1 = pb2[p0 + 1], q2 = pb2[p0 + 2], q3 = pb2[p0 + 3];
        #pragma unroll
        for (int di = 0; di < 4; ++di) {
            float2 a0 = upk2(az2[di][0]);
            float2 a1 = upk2(az2[di][1]);
            float2 a2 = upk2(az2[di][2]);
            float2 a3 = upk2(az2[di][3]);
            float4 r0 = {a0.x + q0, a1.x + q1, a2.x + q2, a3.x + q3};
            float4 r1 = {a0.y + q0, a1.y + q1, a2.y + q2, a3.y + q3};
            *(float4*)(zs + (d0 + 2 * di) * Pp + p0)     = r0;
            *(float4*)(zs + (d0 + 2 * di + 1) * Pp + p0) = r1;
        }
    }
    __syncthreads();
    {
        const float* g  = lngg + 256;
        const float* bb = lnbg + 256;
        #pragma unroll
        for (int r = 0; r < 8; ++r) {
            int row = wid * 8 + r;
            float4 v = *(const float4*)(zs + row * Pp + lane * 4);
            ln_row_write(v, g, bb, outg + ((size_t)b * ROWS + 130 + row) * Pp, lane);
        }
    }

    // ---- feat0 (x projection, rows 0..1) and feat3 (h3 projection, rows 258..260) ----
    if (t >= 384) {
        int p = t - 384;
        z5s[p]      = z0acc0 + pbg[p];
        z5s[Pp + p] = z0acc1 + pbg[p];
    }
    if (t < 384) {
        int j = t >> 7, p = t & 127;
        z5s[(2 + j) * Pp + p] = z3acc + pbg[3 * 128 + p];
    }
    __syncthreads();
    if (wid < 5) {
        int row    = wid;                       // 0,1 -> z0 ; 2,3,4 -> z3
        int feat   = (row < 2) ? 0 : 3;
        int outrow = (row < 2) ? row : (256 + row);  // 258,259,260
        float4 v = *(const float4*)(z5s + row * Pp + lane * 4);
        ln_row_write(v, lngg + feat * 128, lnbg + feat * 128,
                     outg + ((size_t)b * ROWS + outrow) * Pp, lane);
    }
}

extern "C" void kernel_launch(void* const* d_in, const int* in_sizes, int n_in,
                              void* d_out, int out_size) {
    (void)in_sizes; (void)n_in; (void)out_size;
    const float* w0g  = (const float*)d_in[0];
    const float* w1g  = (const float*)d_in[1];
    const float* w2g  = (const float*)d_in[2];
    const float* b0g  = (const float*)d_in[3];
    const float* b1g  = (const float*)d_in[4];
    const float* b2g  = (const float*)d_in[5];
    const float* xg   = (const float*)d_in[6];
    const float* pwg  = (const float*)d_in[7];
    const float* pbg  = (const float*)d_in[8];
    const float* lngg = (const float*)d_in[9];
    const float* lnbg = (const float*)d_in[10];
    float* outg = (float*)d_out;

    cudaFuncSetAttribute(gpf_kernel, cudaFuncAttributeMaxDynamicSharedMemorySize,
                         gpf::SMEM_BYTES);
    gpf_kernel<<<gpf::Bn, gpf::NTHREADS, gpf::SMEM_BYTES>>>(
        w0g, w1g, w2g, b0g, b1g, b2g, xg, pwg, pbg, lngg, lnbg, outg);
}